// round 6
// baseline (speedup 1.0000x reference)
#include <cuda_runtime.h>
#include <math.h>

// Problem dims
#define T_STEPS 8
#define N_PED   2048
#define H_DIM   128
#define D_IN    64
#define G4H     512   // 4*H
#define N_GRP   64
#define GRP_N   32
#define DD_DIM  64
#define NH      4

typedef unsigned long long ull;

// packed f32x2 helpers (sm_100+)
#define FMA2(d, a, b, c) asm("fma.rn.f32x2 %0, %1, %2, %3;" : "=l"(d) : "l"(a), "l"(b), "l"(c))
#define PK2(dst, s) do { unsigned _u = __float_as_uint(s); \
    asm("mov.b64 %0, {%1, %1};" : "=l"(dst) : "r"(_u)); } while (0)
#define PKAB(dst, a, b) do { unsigned _ua = __float_as_uint(a), _ub = __float_as_uint(b); \
    asm("mov.b64 %0, {%1, %2};" : "=l"(dst) : "r"(_ua), "r"(_ub)); } while (0)
#define UNPK2(lo, hi, v) do { unsigned _a, _b; \
    asm("mov.b64 {%0, %1}, %2;" : "=r"(_a), "=r"(_b) : "l"(v)); \
    lo = __uint_as_float(_a); hi = __uint_as_float(_b); } while (0)

// ---------------- scratch (device globals; no allocation) ----------------
__device__ __align__(16) float d_wt  [H_DIM * G4H];   // W_hh permuted
__device__ __align__(16) float d_wit [D_IN * G4H];    // W_ih permuted
__device__ __align__(16) float d_bsum[G4H];           // (b_ih+b_hh) permuted
__device__ __align__(16) float d_h [N_PED * H_DIM];
__device__ __align__(16) float d_th[N_PED * H_DIM];   // tanh(h)
__device__ __align__(16) float d_uv[2 * NH * H_DIM];  // u then v
__device__ __align__(16) float d_gate[N_PED * GRP_N * H_DIM];  // gate[p][j][c]
__device__ __align__(16) float d_m [NH * N_PED * H_DIM];

// ---------------- fast activations ----------------
__device__ __forceinline__ float sigf(float x) {
    return __fdividef(1.f, 1.f + __expf(-x));
}
__device__ __forceinline__ float tanh_f(float x) {
    return 1.f - __fdividef(2.f, __expf(2.f * x) + 1.f);
}

// ---------------- weight prep: permute + bias sum ----------------
__global__ void prep_kernel(const float* __restrict__ W_hh, const float* __restrict__ W_ih,
                            const float* __restrict__ b_ih, const float* __restrict__ b_hh)
{
    int i = blockIdx.x * 256 + threadIdx.x;
    if (i < H_DIM * G4H) {
        int k = i >> 9, q = i & 511;
        int half = q >> 8, tx = (q >> 2) & 63, u = q & 3;
        int n = u * 128 + 2 * tx + half;
        d_wt[i] = W_hh[n * H_DIM + k];
        return;
    }
    int j = i - H_DIM * G4H;
    if (j < D_IN * G4H) {
        int k = j >> 9, q = j & 511;
        int half = q >> 8, tx = (q >> 2) & 63, u = q & 3;
        int n = u * 128 + 2 * tx + half;
        d_wit[j] = W_ih[n * D_IN + k];
        return;
    }
    int b = j - D_IN * G4H;
    if (b < G4H) {
        int half = b >> 8, tx = (b >> 2) & 63, u = b & 3;
        int n = u * 128 + 2 * tx + half;
        d_bsum[b] = b_ih[n] + b_hh[n];
    }
}

// ======================= FAT KERNEL A =======================
// blocks [0,128)        : fused embed + 8-step LSTM (latency-bound)
// blocks [128,1152)     : gate MLP (position-only; FMA-bound, fills stalls)
// blocks [1152,1156)    : uv fold
#define A_LSTM  128
#define A_GATE  1024
#define A_GRID  (A_LSTM + A_GATE + 4)

__global__ __launch_bounds__(256) void fatA(
    const float* __restrict__ h0, const float* __restrict__ c0,
    const float* __restrict__ obs,
    const float* __restrict__ W_emb, const float* __restrict__ b_emb,
    const float* __restrict__ goal, const float* __restrict__ action,
    const float* __restrict__ W_dist, const float* __restrict__ b_dist,
    const float* __restrict__ W_gate, const float* __restrict__ b_gate,
    const float* __restrict__ gat_w, const float* __restrict__ gat_a)
{
    __shared__ __align__(16) char sraw[40960];
    int tid = threadIdx.x;
    int b = blockIdx.x;

    if (b < A_LSTM) {
        // ---------------- LSTM branch ----------------
        float (*h_sh)[H_DIM]      = (float (*)[H_DIM])sraw;                 // 8KB
        float (*x_sh)[16][D_IN]   = (float (*)[16][D_IN])(sraw + 8192);     // 32KB
        int tx = tid & 63, ty = tid >> 6;
        int p0 = b * 16;

        for (int i = tid; i < T_STEPS * 16 * D_IN; i += 256) {
            int t = i >> 10;
            int r = (i >> 6) & 15;
            int c = i & 63;
            const float* op = obs + ((size_t)t * N_PED + p0 + r) * 2;
            float v = fmaf(op[0], W_emb[c], fmaf(op[1], W_emb[64 + c], b_emb[c]));
            x_sh[t][r][c] = fmaxf(v, 0.f);
        }
        {
            float4* dst = (float4*)&h_sh[0][0];
            const float4* src = (const float4*)&h0[(size_t)p0 * H_DIM];
            for (int i = tid; i < 512; i += 256) dst[i] = src[i];
        }
        float c_reg[4][2];
#pragma unroll
        for (int p = 0; p < 4; p++) {
            float2 cv = *(const float2*)&c0[(size_t)(p0 + 4 * ty + p) * H_DIM + 2 * tx];
            c_reg[p][0] = cv.x; c_reg[p][1] = cv.y;
        }
        ulonglong2 binit0 = *(const ulonglong2*)&d_bsum[tx * 4];
        ulonglong2 binit1 = *(const ulonglong2*)&d_bsum[256 + tx * 4];
        __syncthreads();

        const ulonglong2* wt2 = (const ulonglong2*)d_wt;
        const ulonglong2* wi2 = (const ulonglong2*)d_wit;

        for (int t = 0; t < T_STEPS; t++) {
            ull acc[4][4];
#pragma unroll
            for (int p = 0; p < 4; p++) {
                acc[p][0] = binit0.x; acc[p][1] = binit0.y;
                acc[p][2] = binit1.x; acc[p][3] = binit1.y;
            }
#pragma unroll 8
            for (int k = 0; k < H_DIM; k++) {
                ulonglong2 wa = wt2[(k * 2 + 0) * 64 + tx];
                ulonglong2 wb = wt2[(k * 2 + 1) * 64 + tx];
                ull hp[4];
#pragma unroll
                for (int p = 0; p < 4; p++) PK2(hp[p], h_sh[4 * ty + p][k]);
#pragma unroll
                for (int p = 0; p < 4; p++) {
                    FMA2(acc[p][0], hp[p], wa.x, acc[p][0]);
                    FMA2(acc[p][1], hp[p], wa.y, acc[p][1]);
                    FMA2(acc[p][2], hp[p], wb.x, acc[p][2]);
                    FMA2(acc[p][3], hp[p], wb.y, acc[p][3]);
                }
            }
#pragma unroll 8
            for (int k = 0; k < D_IN; k++) {
                ulonglong2 wa = wi2[(k * 2 + 0) * 64 + tx];
                ulonglong2 wb = wi2[(k * 2 + 1) * 64 + tx];
                ull xp[4];
#pragma unroll
                for (int p = 0; p < 4; p++) PK2(xp[p], x_sh[t][4 * ty + p][k]);
#pragma unroll
                for (int p = 0; p < 4; p++) {
                    FMA2(acc[p][0], xp[p], wa.x, acc[p][0]);
                    FMA2(acc[p][1], xp[p], wa.y, acc[p][1]);
                    FMA2(acc[p][2], xp[p], wb.x, acc[p][2]);
                    FMA2(acc[p][3], xp[p], wb.y, acc[p][3]);
                }
            }
            __syncthreads();
#pragma unroll
            for (int p = 0; p < 4; p++) {
#pragma unroll
                for (int half = 0; half < 2; half++) {
                    float iv, fv, gv, ov;
                    UNPK2(iv, fv, acc[p][2 * half]);
                    UNPK2(gv, ov, acc[p][2 * half + 1]);
                    float cn = sigf(fv) * c_reg[p][half] + sigf(iv) * tanh_f(gv);
                    c_reg[p][half] = cn;
                    h_sh[4 * ty + p][2 * tx + half] = sigf(ov) * tanh_f(cn);
                }
            }
            __syncthreads();
        }
        for (int i = tid; i < 16 * H_DIM; i += 256) {
            float v = h_sh[i >> 7][i & 127];
            d_h [(size_t)p0 * H_DIM + i] = v;
            d_th[(size_t)p0 * H_DIM + i] = tanh_f(v);
        }
    } else if (b < A_LSTM + A_GATE) {
        // ---------------- gate MLP branch (position-only) ----------------
        int gb = b - A_LSTM;
        int g  = gb >> 4;
        int ip = gb & 15;
        int half = tid >> 7;
        int c    = tid & 127;
        int i_loc = 2 * ip + half;
        int p = g * GRP_N + i_loc;

        float* t_sh = (float*)sraw;                 // [32][64]  8KB
        float* s_sh = (float*)(sraw + 8192);        // [2][64]
        float* r_sh = (float*)(sraw + 8704);        // [2][32][64] 16KB
        float* pax  = (float*)(sraw + 25088);
        float* pay  = pax + 32;
        float* pgx  = pax + 64;
        float* pgy  = pax + 96;

        if (tid < GRP_N) {
            int q = g * GRP_N + tid;
            pax[tid] = action[q * 2 + 0]; pay[tid] = action[q * 2 + 1];
            pgx[tid] = goal[q * 2 + 0];   pgy[tid] = goal[q * 2 + 1];
        }
        __syncthreads();
        for (int idx = tid; idx < GRP_N * DD_DIM; idx += 256) {
            int j = idx >> 6, d = idx & 63;
            float t = fmaf(pax[j], W_dist[4 * 64 + d],
                      fmaf(pay[j], W_dist[5 * 64 + d],
                      fmaf(pgx[j], W_dist[6 * 64 + d],
                           pgy[j] * W_dist[7 * 64 + d])));
            t_sh[idx] = t;
        }
        if (tid < 2 * DD_DIM) {
            int hh = tid >> 6, d = tid & 63;
            int il = 2 * ip + hh;
            float s = b_dist[d];
            s = fmaf(pax[il], W_dist[0 * 64 + d], s);
            s = fmaf(pay[il], W_dist[1 * 64 + d], s);
            s = fmaf(pgx[il], W_dist[2 * 64 + d], s);
            s = fmaf(pgy[il], W_dist[3 * 64 + d], s);
            s_sh[tid] = s;
        }
        __syncthreads();
        for (int idx = tid; idx < 2 * GRP_N * DD_DIM; idx += 256) {
            int hh = idx >> 11, jd = idx & 2047;
            r_sh[idx] = fmaxf(s_sh[hh * 64 + (jd & 63)] + t_sh[jd], 0.f);
        }
        __syncthreads();

        float bg = b_gate[c];
        const float* rbase = r_sh + half * GRP_N * DD_DIM;
        float* gout = d_gate + (size_t)p * GRP_N * H_DIM;
#pragma unroll
        for (int jt = 0; jt < 4; jt++) {
            int j0 = jt * 8;
            ull acc2[8];
#pragma unroll
            for (int jj = 0; jj < 8; jj++) acc2[jj] = 0ull;
            for (int d0 = 0; d0 < DD_DIM; d0 += 4) {
                float w0 = W_gate[(d0 + 0) * H_DIM + c];
                float w1 = W_gate[(d0 + 1) * H_DIM + c];
                float w2 = W_gate[(d0 + 2) * H_DIM + c];
                float w3 = W_gate[(d0 + 3) * H_DIM + c];
                ull ww0, ww1;
                PKAB(ww0, w0, w1);
                PKAB(ww1, w2, w3);
#pragma unroll
                for (int jj = 0; jj < 8; jj++) {
                    ulonglong2 rv = *(const ulonglong2*)&rbase[(j0 + jj) * DD_DIM + d0];
                    FMA2(acc2[jj], rv.x, ww0, acc2[jj]);
                    FMA2(acc2[jj], rv.y, ww1, acc2[jj]);
                }
            }
#pragma unroll
            for (int jj = 0; jj < 8; jj++) {
                float lo, hi;
                UNPK2(lo, hi, acc2[jj]);
                gout[(j0 + jj) * H_DIM + c] = sigf(lo + hi + bg);
            }
        }
    } else {
        // ---------------- uv fold: u_h = w_h@a1, v_h = w_h@a2 ----------------
        int dot = (b - A_LSTM - A_GATE) * 256 + tid;   // 0..1023
        int sel = dot >> 9;
        int h   = (dot >> 7) & 3;
        int c   = dot & 127;
        const float* a  = gat_a + sel * H_DIM;
        const float* wp = gat_w + ((size_t)h * H_DIM + c) * H_DIM;
        float s = 0.f;
#pragma unroll 8
        for (int o = 0; o < H_DIM; o++) s = fmaf(wp[o], a[o], s);
        d_uv[sel * (NH * H_DIM) + h * H_DIM + c] = s;
    }
}

// ======================= KERNEL B: h-dependent GAT =======================
// grid 1024, 256 threads: group g = b>>4, rows i = 2*(b&15)+half
__global__ __launch_bounds__(256) void gatB(const float* __restrict__ goal_hidden)
{
    __shared__ __align__(16) float gth[2 * GRP_N * H_DIM];  // 32KB
    __shared__ float ah_sh[2][H_DIM];
    __shared__ float sdot[2][NH][GRP_N];
    __shared__ float alpha[2][NH][GRP_N + 1];
    __shared__ float hsu[2][NH], hsv[2][NH];

    int tid = threadIdx.x;
    int b = blockIdx.x;
    int g  = b >> 4;
    int ip = b & 15;
    int half = tid >> 7;
    int c    = tid & 127;
    int i_loc = 2 * ip + half;
    int p = g * GRP_N + i_loc;

    float ahc = d_h[(size_t)p * H_DIM + c];
    float ghc = goal_hidden[(size_t)p * H_DIM + c];
    ah_sh[half][c] = ahc;

    // gth[j][c] = gate*tanh(h_j), diagonal replaced by gh (makes sdot[i]=gh·v)
    {
        const float* gp = d_gate + (size_t)p * GRP_N * H_DIM;
        float* dst = gth + half * GRP_N * H_DIM;
#pragma unroll 4
        for (int j = 0; j < GRP_N; j++) {
            float v = gp[j * H_DIM + c] * d_th[(size_t)(g * GRP_N + j) * H_DIM + c];
            dst[j * H_DIM + c] = (j == i_loc) ? ghc : v;
        }
    }
    __syncthreads();

    // per-head dots: warp w (within half) = head
    {
        int t128 = tid & 127, w = t128 >> 5, lane = t128 & 31;
        const float* uh = d_uv + w * H_DIM;
        const float* vh = d_uv + NH * H_DIM + w * H_DIM;
        float u4[4], v4[4], a4[4];
#pragma unroll
        for (int k = 0; k < 4; k++) {
            int cc = lane + 32 * k;
            u4[k] = uh[cc]; v4[k] = vh[cc];
            a4[k] = ah_sh[half][cc];
        }
        float su = 0.f, sv = 0.f;
#pragma unroll
        for (int k = 0; k < 4; k++) { su = fmaf(a4[k], u4[k], su); sv = fmaf(a4[k], v4[k], sv); }
#pragma unroll
        for (int o = 16; o; o >>= 1) {
            su += __shfl_xor_sync(0xffffffffu, su, o);
            sv += __shfl_xor_sync(0xffffffffu, sv, o);
        }
        if (lane == 0) { hsu[half][w] = su; hsv[half][w] = sv; }
        const float* src = gth + half * GRP_N * H_DIM;
        for (int j = 0; j < GRP_N; j++) {
            float s = 0.f;
#pragma unroll
            for (int k = 0; k < 4; k++)
                s = fmaf(src[j * H_DIM + lane + 32 * k], v4[k], s);
#pragma unroll
            for (int o = 16; o; o >>= 1) s += __shfl_xor_sync(0xffffffffu, s, o);
            if (lane == 0) sdot[half][w][j] = s;
        }
    }
    __syncthreads();

    // softmax over 33 per (half, head) — 8 threads
    if (tid < 8) {
        int hh = tid >> 2, h = tid & 3;
        float su = hsu[hh][h], sv = hsv[hh][h];
        float sc[GRP_N + 1];
        float s0 = su + sv;
        sc[0] = (s0 >= 0.f) ? s0 : 0.2f * s0;
        float mx = sc[0];
#pragma unroll
        for (int j = 0; j < GRP_N; j++) {
            float s = su + sdot[hh][h][j];
            s = (s >= 0.f) ? s : 0.2f * s;
            sc[j + 1] = s;
            mx = fmaxf(mx, s);
        }
        float sum = 0.f;
#pragma unroll
        for (int k = 0; k <= GRP_N; k++) { sc[k] = __expf(sc[k] - mx); sum += sc[k]; }
        float inv = __fdividef(1.f, sum);
#pragma unroll
        for (int k = 0; k <= GRP_N; k++) alpha[hh][h][k] = sc[k] * inv;
    }
    __syncthreads();

    // m[h][c] = alpha0*ah + sum_j alpha_{j+1} * gth[j][c]
    {
        float macc[NH];
#pragma unroll
        for (int h = 0; h < NH; h++) macc[h] = alpha[half][h][0] * ahc;
        const float* src = gth + half * GRP_N * H_DIM;
#pragma unroll 4
        for (int j = 0; j < GRP_N; j++) {
            float gval = src[j * H_DIM + c];
#pragma unroll
            for (int h = 0; h < NH; h++)
                macc[h] = fmaf(alpha[half][h][j + 1], gval, macc[h]);
        }
#pragma unroll
        for (int h = 0; h < NH; h++)
            d_m[((size_t)h * N_PED + p) * H_DIM + c] = macc[h];
    }
}

// ---------------- final: out = relu(0.25 * sum_h m_h @ w_h) + gat_bias ----------------
__global__ __launch_bounds__(128) void g3_kernel(
    const float* __restrict__ gat_w, const float* __restrict__ gat_bias,
    float* __restrict__ out)
{
    const int TP = 8;
    int p0 = blockIdx.x * TP;
    int tid = threadIdx.x;
    __shared__ __align__(16) float m_sh[TP][H_DIM];
    ull acc2[TP];
#pragma unroll
    for (int r = 0; r < TP; r++) acc2[r] = 0ull;

    for (int h = 0; h < NH; h++) {
        __syncthreads();
#pragma unroll
        for (int r = 0; r < TP; r++)
            m_sh[r][tid] = d_m[((size_t)h * N_PED + p0 + r) * H_DIM + tid];
        __syncthreads();
        const float* wh = gat_w + (size_t)h * H_DIM * H_DIM;
        for (int f0 = 0; f0 < H_DIM; f0 += 8) {
            float w0 = wh[(f0 + 0) * H_DIM + tid];
            float w1 = wh[(f0 + 1) * H_DIM + tid];
            float w2 = wh[(f0 + 2) * H_DIM + tid];
            float w3 = wh[(f0 + 3) * H_DIM + tid];
            float w4 = wh[(f0 + 4) * H_DIM + tid];
            float w5 = wh[(f0 + 5) * H_DIM + tid];
            float w6 = wh[(f0 + 6) * H_DIM + tid];
            float w7 = wh[(f0 + 7) * H_DIM + tid];
            ull ww0, ww1, ww2, ww3;
            PKAB(ww0, w0, w1); PKAB(ww1, w2, w3);
            PKAB(ww2, w4, w5); PKAB(ww3, w6, w7);
#pragma unroll
            for (int r = 0; r < TP; r++) {
                ulonglong2 ma = *(const ulonglong2*)&m_sh[r][f0];
                ulonglong2 mb = *(const ulonglong2*)&m_sh[r][f0 + 4];
                FMA2(acc2[r], ma.x, ww0, acc2[r]);
                FMA2(acc2[r], ma.y, ww1, acc2[r]);
                FMA2(acc2[r], mb.x, ww2, acc2[r]);
                FMA2(acc2[r], mb.y, ww3, acc2[r]);
            }
        }
    }
    float bb = gat_bias[tid];
#pragma unroll
    for (int r = 0; r < TP; r++) {
        float lo, hi;
        UNPK2(lo, hi, acc2[r]);
        out[(size_t)(p0 + r) * H_DIM + tid] = fmaxf(0.25f * (lo + hi), 0.f) + bb;
    }
}

// ---------------- host ----------------
extern "C" void kernel_launch(void* const* d_in, const int* in_sizes, int n_in,
                              void* d_out, int out_size)
{
    const float* obs         = (const float*)d_in[0];
    const float* goal_hidden = (const float*)d_in[1];
    const float* goal        = (const float*)d_in[2];
    const float* action      = (const float*)d_in[3];
    const float* h0          = (const float*)d_in[4];
    const float* c0          = (const float*)d_in[5];
    const float* W_emb       = (const float*)d_in[6];
    const float* b_emb       = (const float*)d_in[7];
    const float* W_ih        = (const float*)d_in[8];
    const float* W_hh        = (const float*)d_in[9];
    const float* b_ih        = (const float*)d_in[10];
    const float* b_hh        = (const float*)d_in[11];
    const float* W_dist      = (const float*)d_in[12];
    const float* b_dist      = (const float*)d_in[13];
    const float* W_gate      = (const float*)d_in[14];
    const float* b_gate      = (const float*)d_in[15];
    const float* gat_w       = (const float*)d_in[16];
    const float* gat_a       = (const float*)d_in[17];
    const float* gat_bias    = (const float*)d_in[18];
    float* out = (float*)d_out;

    {
        int total = H_DIM * G4H + D_IN * G4H + G4H;
        prep_kernel<<<(total + 255) / 256, 256>>>(W_hh, W_ih, b_ih, b_hh);
    }

    // fat kernel: LSTM (blocks 0..127) || gate MLP (128..1151) || uv (1152..1155)
    fatA<<<A_GRID, 256>>>(h0, c0, obs, W_emb, b_emb,
                          goal, action, W_dist, b_dist, W_gate, b_gate,
                          gat_w, gat_a);

    // h-dependent GAT remainder
    gatB<<<1024, 256>>>(goal_hidden);

    g3_kernel<<<N_PED / 8, 128>>>(gat_w, gat_bias, out);
}

// round 7
// speedup vs baseline: 1.4849x; 1.4849x over previous
#include <cuda_runtime.h>
#include <math.h>

// Problem dims
#define T_STEPS 8
#define N_PED   2048
#define H_DIM   128
#define D_IN    64
#define G4H     512   // 4*H
#define N_GRP   64
#define GRP_N   32
#define DD_DIM  64
#define NH      4

typedef unsigned long long ull;

// packed f32x2 helpers (sm_100+)
#define FMA2(d, a, b, c) asm("fma.rn.f32x2 %0, %1, %2, %3;" : "=l"(d) : "l"(a), "l"(b), "l"(c))
#define PK2(dst, s) do { unsigned _u = __float_as_uint(s); \
    asm("mov.b64 %0, {%1, %1};" : "=l"(dst) : "r"(_u)); } while (0)
#define PKAB(dst, a, b) do { unsigned _ua = __float_as_uint(a), _ub = __float_as_uint(b); \
    asm("mov.b64 %0, {%1, %2};" : "=l"(dst) : "r"(_ua), "r"(_ub)); } while (0)
#define UNPK2(lo, hi, v) do { unsigned _a, _b; \
    asm("mov.b64 {%0, %1}, %2;" : "=r"(_a), "=r"(_b) : "l"(v)); \
    lo = __uint_as_float(_a); hi = __uint_as_float(_b); } while (0)

// ---------------- scratch (device globals; no allocation) ----------------
// Weight layout: d_wt2[k][ch][u] with u in (i,f,g,o): one LDG.128 per (k,ch).
__device__ __align__(16) float d_wt2 [H_DIM * G4H];
__device__ __align__(16) float d_wit2[D_IN * G4H];
__device__ __align__(16) float d_bsum2[G4H];          // [ch][u]
__device__ __align__(16) float d_h [N_PED * H_DIM];
__device__ __align__(16) float d_th[N_PED * H_DIM];   // tanh(h)
__device__ __align__(16) float d_uv[2 * NH * H_DIM];  // u then v
__device__ __align__(16) float d_gate[N_PED * GRP_N * H_DIM];  // gate[p][j][c]
__device__ __align__(16) float d_m [N_PED * G4H];     // m_cat[p][h*128+f]

// ---------------- fast activations ----------------
__device__ __forceinline__ float sigf(float x) {
    return __fdividef(1.f, 1.f + __expf(-x));
}
__device__ __forceinline__ float tanh_f(float x) {
    return 1.f - __fdividef(2.f, __expf(2.f * x) + 1.f);
}

// ---------------- weight prep: permute to [k][ch][u] + bias sum ----------------
__global__ void prep_kernel(const float* __restrict__ W_hh, const float* __restrict__ W_ih,
                            const float* __restrict__ b_ih, const float* __restrict__ b_hh)
{
    int i = blockIdx.x * 256 + threadIdx.x;
    if (i < H_DIM * G4H) {
        int k = i >> 9, q = i & 511;
        int ch = q >> 2, u = q & 3;
        d_wt2[i] = W_hh[(u * 128 + ch) * H_DIM + k];
        return;
    }
    int j = i - H_DIM * G4H;
    if (j < D_IN * G4H) {
        int k = j >> 9, q = j & 511;
        int ch = q >> 2, u = q & 3;
        d_wit2[j] = W_ih[(u * 128 + ch) * D_IN + k];
        return;
    }
    int b = j - D_IN * G4H;
    if (b < G4H) {
        int ch = b >> 2, u = b & 3;
        int n = u * 128 + ch;
        d_bsum2[b] = b_ih[n] + b_hh[n];
    }
}

// ---------------- u_h = w_h @ a1, v_h = w_h @ a2 (1 warp per dot) ----------------
__global__ void uv_kernel(const float* __restrict__ gat_w,
                          const float* __restrict__ gat_a)
{
    int w = (blockIdx.x << 2) + (threadIdx.x >> 5);   // 0..1023
    int lane = threadIdx.x & 31;
    int sel = w >> 9;
    int h   = (w >> 7) & 3;
    int c   = w & 127;
    const float* a  = gat_a + sel * H_DIM;
    const float* wp = gat_w + ((size_t)h * H_DIM + c) * H_DIM;
    float s = 0.f;
#pragma unroll
    for (int o = lane; o < H_DIM; o += 32) s = fmaf(wp[o], a[o], s);
#pragma unroll
    for (int o = 16; o; o >>= 1) s += __shfl_xor_sync(0xffffffffu, s, o);
    if (lane == 0) d_uv[sel * (NH * H_DIM) + h * H_DIM + c] = s;
}

// ---------------- fused embed + 8-step LSTM: 512 threads ----------------
// ch = tid&127 owns channel ch (all 4 gates); ty = tid>>7 owns peds 4ty..4ty+3.
// Per k: one LDG.128 = (i,f,g,o) weights for this channel -> 8 FMA2 (4 peds).
__global__ __launch_bounds__(512) void lstm512(
    const float* __restrict__ h0, const float* __restrict__ c0,
    const float* __restrict__ obs,
    const float* __restrict__ W_emb, const float* __restrict__ b_emb)
{
    __shared__ __align__(16) float h_sh[16][H_DIM];          // 8KB
    __shared__ __align__(16) float x_sh[T_STEPS][16][D_IN];  // 32KB
    int tid = threadIdx.x;
    int ch = tid & 127, ty = tid >> 7;
    int p0 = blockIdx.x * 16;

    // embed x for 16 peds, 8 timesteps
    for (int i = tid; i < T_STEPS * 16 * D_IN; i += 512) {
        int t = i >> 10;
        int r = (i >> 6) & 15;
        int c = i & 63;
        const float* op = obs + ((size_t)t * N_PED + p0 + r) * 2;
        float v = fmaf(op[0], W_emb[c], fmaf(op[1], W_emb[64 + c], b_emb[c]));
        x_sh[t][r][c] = fmaxf(v, 0.f);
    }
    // stage h0
    {
        float4* dst = (float4*)&h_sh[0][0];
        const float4* src = (const float4*)&h0[(size_t)p0 * H_DIM];
        for (int i = tid; i < 512; i += 512) dst[i] = src[i];
    }
    // c in registers (4 peds, 1 channel)
    float c_reg[4];
#pragma unroll
    for (int p = 0; p < 4; p++)
        c_reg[p] = c0[(size_t)(p0 + 4 * ty + p) * H_DIM + ch];
    ulonglong2 bi = *(const ulonglong2*)&d_bsum2[ch * 4];
    __syncthreads();

    const ulonglong2* wt2 = (const ulonglong2*)d_wt2;   // idx k*128 + ch
    const ulonglong2* wi2 = (const ulonglong2*)d_wit2;

    for (int t = 0; t < T_STEPS; t++) {
        ull acc[4][2];
#pragma unroll
        for (int p = 0; p < 4; p++) { acc[p][0] = bi.x; acc[p][1] = bi.y; }
        // recurrent: K = 128
#pragma unroll 8
        for (int k = 0; k < H_DIM; k++) {
            ulonglong2 wv = wt2[k * 128 + ch];
            ull hp[4];
#pragma unroll
            for (int p = 0; p < 4; p++) PK2(hp[p], h_sh[4 * ty + p][k]);
#pragma unroll
            for (int p = 0; p < 4; p++) {
                FMA2(acc[p][0], hp[p], wv.x, acc[p][0]);
                FMA2(acc[p][1], hp[p], wv.y, acc[p][1]);
            }
        }
        // input: K = 64
#pragma unroll 8
        for (int k = 0; k < D_IN; k++) {
            ulonglong2 wv = wi2[k * 128 + ch];
            ull xp[4];
#pragma unroll
            for (int p = 0; p < 4; p++) PK2(xp[p], x_sh[t][4 * ty + p][k]);
#pragma unroll
            for (int p = 0; p < 4; p++) {
                FMA2(acc[p][0], xp[p], wv.x, acc[p][0]);
                FMA2(acc[p][1], xp[p], wv.y, acc[p][1]);
            }
        }
        __syncthreads();
#pragma unroll
        for (int p = 0; p < 4; p++) {
            float iv, fv, gv, ov;
            UNPK2(iv, fv, acc[p][0]);
            UNPK2(gv, ov, acc[p][1]);
            float cn = sigf(fv) * c_reg[p] + sigf(iv) * tanh_f(gv);
            c_reg[p] = cn;
            h_sh[4 * ty + p][ch] = sigf(ov) * tanh_f(cn);
        }
        __syncthreads();
    }
    for (int i = tid; i < 16 * H_DIM; i += 512) {
        float v = h_sh[i >> 7][i & 127];
        d_h [(size_t)p0 * H_DIM + i] = v;
        d_th[(size_t)p0 * H_DIM + i] = tanh_f(v);
    }
}

// ---------------- gate MLP (position-only), standalone ----------------
// 1024 blocks x 256 thr: group g = b>>4, rows 2*(b&15)+half
__global__ __launch_bounds__(256) void gateMLP(
    const float* __restrict__ goal, const float* __restrict__ action,
    const float* __restrict__ W_dist, const float* __restrict__ b_dist,
    const float* __restrict__ W_gate, const float* __restrict__ b_gate)
{
    __shared__ __align__(16) float t_sh[GRP_N * DD_DIM];       // 8KB
    __shared__ __align__(16) float s_sh[2 * DD_DIM];
    __shared__ __align__(16) float r_sh[2 * GRP_N * DD_DIM];   // 16KB
    __shared__ float pax[GRP_N], pay[GRP_N], pgx[GRP_N], pgy[GRP_N];

    int tid = threadIdx.x;
    int b = blockIdx.x;
    int g  = b >> 4;
    int ip = b & 15;
    int half = tid >> 7;
    int c    = tid & 127;
    int i_loc = 2 * ip + half;
    int p = g * GRP_N + i_loc;

    if (tid < GRP_N) {
        int q = g * GRP_N + tid;
        pax[tid] = action[q * 2 + 0]; pay[tid] = action[q * 2 + 1];
        pgx[tid] = goal[q * 2 + 0];   pgy[tid] = goal[q * 2 + 1];
    }
    __syncthreads();
    for (int idx = tid; idx < GRP_N * DD_DIM; idx += 256) {
        int j = idx >> 6, d = idx & 63;
        float t = fmaf(pax[j], W_dist[4 * 64 + d],
                  fmaf(pay[j], W_dist[5 * 64 + d],
                  fmaf(pgx[j], W_dist[6 * 64 + d],
                       pgy[j] * W_dist[7 * 64 + d])));
        t_sh[idx] = t;
    }
    if (tid < 2 * DD_DIM) {
        int hh = tid >> 6, d = tid & 63;
        int il = 2 * ip + hh;
        float s = b_dist[d];
        s = fmaf(pax[il], W_dist[0 * 64 + d], s);
        s = fmaf(pay[il], W_dist[1 * 64 + d], s);
        s = fmaf(pgx[il], W_dist[2 * 64 + d], s);
        s = fmaf(pgy[il], W_dist[3 * 64 + d], s);
        s_sh[tid] = s;
    }
    __syncthreads();
    for (int idx = tid; idx < 2 * GRP_N * DD_DIM; idx += 256) {
        int hh = idx >> 11, jd = idx & 2047;
        r_sh[idx] = fmaxf(s_sh[hh * 64 + (jd & 63)] + t_sh[jd], 0.f);
    }
    __syncthreads();

    float bg = b_gate[c];
    const float* rbase = r_sh + half * GRP_N * DD_DIM;
    float* gout = d_gate + (size_t)p * GRP_N * H_DIM;
#pragma unroll
    for (int jt = 0; jt < 4; jt++) {
        int j0 = jt * 8;
        ull acc2[8];
#pragma unroll
        for (int jj = 0; jj < 8; jj++) acc2[jj] = 0ull;
        for (int d0 = 0; d0 < DD_DIM; d0 += 4) {
            float w0 = W_gate[(d0 + 0) * H_DIM + c];
            float w1 = W_gate[(d0 + 1) * H_DIM + c];
            float w2 = W_gate[(d0 + 2) * H_DIM + c];
            float w3 = W_gate[(d0 + 3) * H_DIM + c];
            ull ww0, ww1;
            PKAB(ww0, w0, w1);
            PKAB(ww1, w2, w3);
#pragma unroll
            for (int jj = 0; jj < 8; jj++) {
                ulonglong2 rv = *(const ulonglong2*)&rbase[(j0 + jj) * DD_DIM + d0];
                FMA2(acc2[jj], rv.x, ww0, acc2[jj]);
                FMA2(acc2[jj], rv.y, ww1, acc2[jj]);
            }
        }
#pragma unroll
        for (int jj = 0; jj < 8; jj++) {
            float lo, hi;
            UNPK2(lo, hi, acc2[jj]);
            gout[(j0 + jj) * H_DIM + c] = sigf(lo + hi + bg);
        }
    }
}

// ---------------- KERNEL B: h-dependent GAT ----------------
__global__ __launch_bounds__(256) void gatB(const float* __restrict__ goal_hidden)
{
    __shared__ __align__(16) float gth[2 * GRP_N * H_DIM];  // 32KB
    __shared__ float ah_sh[2][H_DIM];
    __shared__ float sdot[2][NH][GRP_N];
    __shared__ float alpha[2][NH][GRP_N + 1];
    __shared__ float hsu[2][NH], hsv[2][NH];

    int tid = threadIdx.x;
    int b = blockIdx.x;
    int g  = b >> 4;
    int ip = b & 15;
    int half = tid >> 7;
    int c    = tid & 127;
    int i_loc = 2 * ip + half;
    int p = g * GRP_N + i_loc;

    float ahc = d_h[(size_t)p * H_DIM + c];
    float ghc = goal_hidden[(size_t)p * H_DIM + c];
    ah_sh[half][c] = ahc;

    {
        const float* gp = d_gate + (size_t)p * GRP_N * H_DIM;
        float* dst = gth + half * GRP_N * H_DIM;
#pragma unroll 4
        for (int j = 0; j < GRP_N; j++) {
            float v = gp[j * H_DIM + c] * d_th[(size_t)(g * GRP_N + j) * H_DIM + c];
            dst[j * H_DIM + c] = (j == i_loc) ? ghc : v;
        }
    }
    __syncthreads();

    {
        int t128 = tid & 127, w = t128 >> 5, lane = t128 & 31;
        const float* uh = d_uv + w * H_DIM;
        const float* vh = d_uv + NH * H_DIM + w * H_DIM;
        float u4[4], v4[4], a4[4];
#pragma unroll
        for (int k = 0; k < 4; k++) {
            int cc = lane + 32 * k;
            u4[k] = uh[cc]; v4[k] = vh[cc];
            a4[k] = ah_sh[half][cc];
        }
        float su = 0.f, sv = 0.f;
#pragma unroll
        for (int k = 0; k < 4; k++) { su = fmaf(a4[k], u4[k], su); sv = fmaf(a4[k], v4[k], sv); }
#pragma unroll
        for (int o = 16; o; o >>= 1) {
            su += __shfl_xor_sync(0xffffffffu, su, o);
            sv += __shfl_xor_sync(0xffffffffu, sv, o);
        }
        if (lane == 0) { hsu[half][w] = su; hsv[half][w] = sv; }
        const float* src = gth + half * GRP_N * H_DIM;
        for (int j = 0; j < GRP_N; j++) {
            float s = 0.f;
#pragma unroll
            for (int k = 0; k < 4; k++)
                s = fmaf(src[j * H_DIM + lane + 32 * k], v4[k], s);
#pragma unroll
            for (int o = 16; o; o >>= 1) s += __shfl_xor_sync(0xffffffffu, s, o);
            if (lane == 0) sdot[half][w][j] = s;
        }
    }
    __syncthreads();

    if (tid < 8) {
        int hh = tid >> 2, h = tid & 3;
        float su = hsu[hh][h], sv = hsv[hh][h];
        float sc[GRP_N + 1];
        float s0 = su + sv;
        sc[0] = (s0 >= 0.f) ? s0 : 0.2f * s0;
        float mx = sc[0];
#pragma unroll
        for (int j = 0; j < GRP_N; j++) {
            float s = su + sdot[hh][h][j];
            s = (s >= 0.f) ? s : 0.2f * s;
            sc[j + 1] = s;
            mx = fmaxf(mx, s);
        }
        float sum = 0.f;
#pragma unroll
        for (int k = 0; k <= GRP_N; k++) { sc[k] = __expf(sc[k] - mx); sum += sc[k]; }
        float inv = __fdividef(1.f, sum);
#pragma unroll
        for (int k = 0; k <= GRP_N; k++) alpha[hh][h][k] = sc[k] * inv;
    }
    __syncthreads();

    // m_cat[p][h*128+c]
    {
        float macc[NH];
#pragma unroll
        for (int h = 0; h < NH; h++) macc[h] = alpha[half][h][0] * ahc;
        const float* src = gth + half * GRP_N * H_DIM;
#pragma unroll 4
        for (int j = 0; j < GRP_N; j++) {
            float gval = src[j * H_DIM + c];
#pragma unroll
            for (int h = 0; h < NH; h++)
                macc[h] = fmaf(alpha[half][h][j + 1], gval, macc[h]);
        }
#pragma unroll
        for (int h = 0; h < NH; h++)
            d_m[(size_t)p * G4H + h * H_DIM + c] = macc[h];
    }
}

// ---------------- g3: out = relu(0.25 * m_cat @ w_cat) + bias ----------------
// GEMM M=2048 N=128 K=512; w_cat = gat_w (already [h*128+f][c] contiguous).
// 128 blocks x 256 thr: 16 peds/block; thread = cols (2tx,2tx+1) x 4 peds.
__global__ __launch_bounds__(256) void g3_kernel(
    const float* __restrict__ gat_w, const float* __restrict__ gat_bias,
    float* __restrict__ out)
{
    __shared__ __align__(16) float m_sh[16][G4H];   // 32KB
    int tid = threadIdx.x;
    int tx = tid & 63, ty = tid >> 6;
    int p0 = blockIdx.x * 16;

    {
        float4* dst = (float4*)&m_sh[0][0];
        const float4* src = (const float4*)&d_m[(size_t)p0 * G4H];
        for (int i = tid; i < 2048; i += 256) dst[i] = src[i];
    }
    __syncthreads();

    ull acc[4];
#pragma unroll
    for (int p = 0; p < 4; p++) acc[p] = 0ull;
#pragma unroll 8
    for (int k = 0; k < G4H; k++) {
        ull wv = *(const ull*)&gat_w[(size_t)k * H_DIM + 2 * tx];
        ull mp[4];
#pragma unroll
        for (int p = 0; p < 4; p++) PK2(mp[p], m_sh[4 * ty + p][k]);
#pragma unroll
        for (int p = 0; p < 4; p++) FMA2(acc[p], mp[p], wv, acc[p]);
    }
    float b0 = gat_bias[2 * tx], b1 = gat_bias[2 * tx + 1];
#pragma unroll
    for (int p = 0; p < 4; p++) {
        float lo, hi;
        UNPK2(lo, hi, acc[p]);
        float2 o2;
        o2.x = fmaxf(0.25f * lo, 0.f) + b0;
        o2.y = fmaxf(0.25f * hi, 0.f) + b1;
        *(float2*)&out[(size_t)(p0 + 4 * ty + p) * H_DIM + 2 * tx] = o2;
    }
}

// ---------------- host ----------------
extern "C" void kernel_launch(void* const* d_in, const int* in_sizes, int n_in,
                              void* d_out, int out_size)
{
    const float* obs         = (const float*)d_in[0];
    const float* goal_hidden = (const float*)d_in[1];
    const float* goal        = (const float*)d_in[2];
    const float* action      = (const float*)d_in[3];
    const float* h0          = (const float*)d_in[4];
    const float* c0          = (const float*)d_in[5];
    const float* W_emb       = (const float*)d_in[6];
    const float* b_emb       = (const float*)d_in[7];
    const float* W_ih        = (const float*)d_in[8];
    const float* W_hh        = (const float*)d_in[9];
    const float* b_ih        = (const float*)d_in[10];
    const float* b_hh        = (const float*)d_in[11];
    const float* W_dist      = (const float*)d_in[12];
    const float* b_dist      = (const float*)d_in[13];
    const float* W_gate      = (const float*)d_in[14];
    const float* b_gate      = (const float*)d_in[15];
    const float* gat_w       = (const float*)d_in[16];
    const float* gat_a       = (const float*)d_in[17];
    const float* gat_bias    = (const float*)d_in[18];
    float* out = (float*)d_out;

    {
        int total = H_DIM * G4H + D_IN * G4H + G4H;
        prep_kernel<<<(total + 255) / 256, 256>>>(W_hh, W_ih, b_ih, b_hh);
    }
    uv_kernel<<<256, 128>>>(gat_w, gat_a);
    gateMLP<<<1024, 256>>>(goal, action, W_dist, b_dist, W_gate, b_gate);

    lstm512<<<N_PED / 16, 512>>>(h0, c0, obs, W_emb, b_emb);

    gatB<<<1024, 256>>>(goal_hidden);
    g3_kernel<<<N_PED / 16, 256>>>(gat_w, gat_bias, out);
}